// round 2
// baseline (speedup 1.0000x reference)
#include <cuda_runtime.h>
#include <math.h>

#define NN 4096
#define DD 256
#define SLOTS 16        // NN / 256
#define CAPC 1024       // contiguous support-list capacity

// ---------------- device scratch ----------------
__device__ float g_negT[(size_t)NN * NN];   // -cost^T
__device__ float g_tau_col[NN];
__device__ float g_beta[(size_t)NN * DD];
__device__ float g_alpha[(size_t)NN * DD];
__device__ float g_v1[DD];
__device__ float g_v2[DD];
__device__ float g_y;

// ---------------- reduction helpers ----------------
__device__ __forceinline__ float warpRedSum(float v) {
#pragma unroll
    for (int o = 16; o > 0; o >>= 1) v += __shfl_xor_sync(0xffffffffu, v, o);
    return v;
}

__device__ __forceinline__ float blockReduceSum(float v, float* red, int tid) {
    v = warpRedSum(v);
    if ((tid & 31) == 0) red[tid >> 5] = v;
    __syncthreads();
    if (tid == 0) {
        float s = 0.f;
#pragma unroll
        for (int i = 0; i < 8; i++) s += red[i];
        red[32] = s;
    }
    __syncthreads();
    float r = red[32];
    __syncthreads();
    return r;
}

__device__ __forceinline__ void blockReduce2(float& a, float& b, float* red, int tid) {
    a = warpRedSum(a);
    b = warpRedSum(b);
    if ((tid & 31) == 0) { red[tid >> 5] = a; red[8 + (tid >> 5)] = b; }
    __syncthreads();
    if (tid == 0) {
        float s = 0.f, c = 0.f;
#pragma unroll
        for (int i = 0; i < 8; i++) { s += red[i]; c += red[8 + i]; }
        red[32] = s; red[33] = c;
    }
    __syncthreads();
    a = red[32];
    b = red[33];
    __syncthreads();
}

__device__ __forceinline__ int blockScanExcl(int cnt, int& total, int tid) {
    __shared__ int warp_tot[8];
    const unsigned mask = 0xffffffffu;
    int lane = tid & 31, w = tid >> 5;
    int incl = cnt;
#pragma unroll
    for (int o = 1; o < 32; o <<= 1) {
        int n = __shfl_up_sync(mask, incl, o);
        if (lane >= o) incl += n;
    }
    if (lane == 31) warp_tot[w] = incl;
    __syncthreads();
    if (w == 0) {
        int t = (lane < 8) ? warp_tot[lane] : 0;
#pragma unroll
        for (int o = 1; o < 8; o <<= 1) {
            int n = __shfl_up_sync(mask, t, o);
            if (lane >= o) t += n;
        }
        if (lane < 8) warp_tot[lane] = t;
    }
    __syncthreads();
    int warp_off = (w == 0) ? 0 : warp_tot[w - 1];
    total = warp_tot[7];
    __syncthreads();
    return warp_off + incl - cnt;
}

// ---------------- sparsemax core: shrinking candidate list ----------------
// xrow: NN floats (negated on load if negate). Computes tau exactly, optionally
// writes the alignment row (reconstructed from a fresh global read), stores tau,
// and accumulates mix_out[row,:] = sum_j p_j * V[j,:].
__device__ __forceinline__ void spmax_core(const float* __restrict__ xrow, bool negate,
                                           float* __restrict__ align_row,
                                           float* __restrict__ tau_store,
                                           const float* __restrict__ V,
                                           float* __restrict__ mix_out, int row) {
    __shared__ float cv[SLOTS * 256];          // candidate values (thread-private cols)
    __shared__ unsigned short ci[SLOTS * 256]; // candidate indices
    __shared__ float s_val[CAPC];
    __shared__ unsigned short s_idx[CAPC];
    __shared__ float red[40];
    int tid = threadIdx.x;  // 256 threads

    float sgn = negate ? -1.f : 1.f;

    // coalesced load -> thread-private candidate columns, running sum
    float lsum = 0.f;
#pragma unroll
    for (int k = 0; k < 4; k++) {
        int j = tid * 4 + k * 1024;
        float4 v = *(const float4*)(xrow + j);
        v.x *= sgn; v.y *= sgn; v.z *= sgn; v.w *= sgn;
        int s = k * 4;
        cv[(s + 0) * 256 + tid] = v.x; ci[(s + 0) * 256 + tid] = (unsigned short)(j + 0);
        cv[(s + 1) * 256 + tid] = v.y; ci[(s + 1) * 256 + tid] = (unsigned short)(j + 1);
        cv[(s + 2) * 256 + tid] = v.z; ci[(s + 2) * 256 + tid] = (unsigned short)(j + 2);
        cv[(s + 3) * 256 + tid] = v.w; ci[(s + 3) * 256 + tid] = (unsigned short)(j + 3);
        lsum += (v.x + v.y) + (v.z + v.w);
    }
    int cnt = SLOTS;

    float total = blockReduceSum(lsum, red, tid);
    float tau = (total - 1.0f) * (1.0f / NN);
    int kprev = NN;

    // Michelot with in-place per-thread compaction (support shrinks monotonically)
    for (int it = 0; it < 48; ++it) {
        float ls = 0.f;
        int newc = 0;
        for (int s = 0; s < cnt; s++) {
            float v = cv[s * 256 + tid];
            if (v > tau) {
                cv[newc * 256 + tid] = v;
                ci[newc * 256 + tid] = ci[s * 256 + tid];
                ls += v;
                newc++;
            }
        }
        cnt = newc;
        float lc = (float)newc;
        blockReduce2(ls, lc, red, tid);
        int k = (int)lc;
        if (k == kprev) break;
        tau = (ls - 1.0f) / (float)k;
        kprev = k;
    }

    if (tau_store && tid == 0) *tau_store = tau;

    // write alignment row by re-reading the source (coalesced; frees smem for occupancy)
    if (align_row) {
#pragma unroll
        for (int k = 0; k < 4; k++) {
            int j = tid * 4 + k * 1024;
            float4 v = *(const float4*)(xrow + j);
            float4 o;
            o.x = fmaxf(sgn * v.x - tau, 0.f);
            o.y = fmaxf(sgn * v.y - tau, 0.f);
            o.z = fmaxf(sgn * v.z - tau, 0.f);
            o.w = fmaxf(sgn * v.w - tau, 0.f);
            *(float4*)(align_row + j) = o;
        }
    }

    // compact surviving candidates (== support) into one contiguous list
    int nnz;
    int base = blockScanExcl(cnt, nnz, tid);
    if (nnz <= CAPC) {
        for (int s = 0; s < cnt; s++) {
            s_val[base + s] = cv[s * 256 + tid];
            s_idx[base + s] = ci[s * 256 + tid];
        }
    }
    __syncthreads();

    // mix: out[row, d] = sum_{j in support} (x_j - tau) * V[j, d], d = tid
    float acc = 0.f;
    if (nnz <= CAPC) {
        for (int n = 0; n < nnz; n++) {
            int j = (int)s_idx[n];
            acc = fmaf(s_val[n] - tau, V[(size_t)j * DD + tid], acc);
        }
    } else {
        // fallback (never expected): dense pass over the global row
        for (int j = 0; j < NN; j++) {
            float p = sgn * xrow[j] - tau;
            if (p > 0.f) acc = fmaf(p, V[(size_t)j * DD + tid], acc);
        }
    }
    mix_out[(size_t)row * DD + tid] = acc;
}

// ---------------- kernels ----------------
__global__ void zero_kernel() {
    int t = threadIdx.x;
    g_v1[t] = 0.f;
    g_v2[t] = 0.f;
}

__global__ void transpose_neg_kernel(const float* __restrict__ in) {
    __shared__ float t[32][33];
    int bx = blockIdx.x * 32, by = blockIdx.y * 32;
    int tx = threadIdx.x, ty = threadIdx.y;
#pragma unroll
    for (int dy = 0; dy < 32; dy += 8)
        t[ty + dy][tx] = -in[(size_t)(by + ty + dy) * NN + bx + tx];
    __syncthreads();
#pragma unroll
    for (int dy = 0; dy < 32; dy += 8)
        g_negT[(size_t)(bx + ty + dy) * NN + by + tx] = t[tx][ty + dy];
}

__global__ __launch_bounds__(256) void spmax_row_kernel(const float* __restrict__ cost,
                                                        float* __restrict__ a0,
                                                        const float* __restrict__ colvecs) {
    int row = blockIdx.x;
    spmax_core(cost + (size_t)row * NN, true, a0 + (size_t)row * NN, nullptr,
               colvecs, g_beta, row);
}

__global__ __launch_bounds__(256) void spmax_col_kernel(const float* __restrict__ rowvecs) {
    int row = blockIdx.x;   // = column index of the original cost matrix
    spmax_core(g_negT + (size_t)row * NN, false, nullptr, &g_tau_col[row],
               rowvecs, g_alpha, row);
}

// align1[i, j] = max(-cost[i,j] - tau_col[j], 0), coalesced
__global__ void col_align_kernel(const float* __restrict__ cost, float* __restrict__ out) {
    size_t idx = ((size_t)blockIdx.x * blockDim.x + threadIdx.x) * 4;
    int j = (int)(idx & (NN - 1));
    float4 c = *(const float4*)(cost + idx);
    float4 o;
    o.x = fmaxf(-c.x - g_tau_col[j + 0], 0.f);
    o.y = fmaxf(-c.y - g_tau_col[j + 1], 0.f);
    o.z = fmaxf(-c.z - g_tau_col[j + 2], 0.f);
    o.w = fmaxf(-c.w - g_tau_col[j + 3], 0.f);
    *(float4*)(out + idx) = o;
}

// partial sums of leaky_relu(X @ W + b) over 16 rows per block
__global__ __launch_bounds__(256) void g_mean_kernel(const float* __restrict__ Wg,
                                                     const float* __restrict__ bg,
                                                     int which) {
    const float* Xall = which ? g_alpha : g_beta;
    float* gv = which ? g_v2 : g_v1;
    __shared__ float xs[16 * 256];
    int tid = threadIdx.x;
    size_t r0 = (size_t)blockIdx.x * 16;
#pragma unroll
    for (int r = 0; r < 16; r++) xs[r * 256 + tid] = Xall[(r0 + r) * 256 + tid];
    __syncthreads();

    float acc[16];
#pragma unroll
    for (int r = 0; r < 16; r++) acc[r] = 0.f;
#pragma unroll 4
    for (int k = 0; k < 256; k++) {
        float w = Wg[k * 256 + tid];
#pragma unroll
        for (int r = 0; r < 16; r++) acc[r] = fmaf(xs[r * 256 + k], w, acc[r]);
    }
    float bb = bg[tid], s = 0.f;
#pragma unroll
    for (int r = 0; r < 16; r++) {
        float z = acc[r] + bb;
        s += (z > 0.f) ? z : 0.2f * z;
    }
    atomicAdd(&gv[tid], s);
}

__global__ void cosine_kernel() {
    __shared__ float red[40];
    int tid = threadIdx.x;
    float v1 = g_v1[tid] * (1.0f / NN);
    float v2 = g_v2[tid] * (1.0f / NN);
    float d = v1 * v2, a = v1 * v1, b = v2 * v2;
    d = blockReduceSum(d, red, tid);
    a = blockReduceSum(a, red, tid);
    b = blockReduceSum(b, red, tid);
    if (tid == 0)
        g_y = 1.0f - d / (sqrtf(a) * sqrtf(b) + 1e-8f);
}

__global__ void fill_kernel(float* __restrict__ out) {
    float y = g_y;
    size_t idx = ((size_t)blockIdx.x * blockDim.x + threadIdx.x) * 4;
    *(float4*)(out + idx) = make_float4(y, y, y, y);
}

// ---------------- launch ----------------
extern "C" void kernel_launch(void* const* d_in, const int* in_sizes, int n_in,
                              void* d_out, int out_size) {
    const float* row_vecs    = (const float*)d_in[0];
    const float* column_vecs = (const float*)d_in[1];
    const float* cost        = (const float*)d_in[2];
    const float* W_G         = (const float*)d_in[3];
    const float* b_G         = (const float*)d_in[4];

    float* out      = (float*)d_out;
    float* cost_out = out;
    float* a0       = out + (size_t)NN * NN;
    float* a1       = out + 2 * (size_t)NN * NN;

    (void)in_sizes; (void)n_in; (void)out_size;

    zero_kernel<<<1, 256>>>();
    transpose_neg_kernel<<<dim3(NN / 32, NN / 32), dim3(32, 8)>>>(cost);
    spmax_row_kernel<<<NN, 256>>>(cost, a0, column_vecs);
    spmax_col_kernel<<<NN, 256>>>(row_vecs);
    col_align_kernel<<<(NN * (size_t)NN) / (4 * 256), 256>>>(cost, a1);
    g_mean_kernel<<<NN / 16, 256>>>(W_G, b_G, 0);
    g_mean_kernel<<<NN / 16, 256>>>(W_G, b_G, 1);
    cosine_kernel<<<1, 256>>>();
    fill_kernel<<<(NN * (size_t)NN) / (4 * 256), 256>>>(cost_out);
}

// round 3
// speedup vs baseline: 1.2854x; 1.2854x over previous
#include <cuda_runtime.h>
#include <math.h>

#define NN 4096
#define DD 256
#define CAPS 1024   // support-list capacity (typical nnz ~ 6)

// ---------------- device scratch ----------------
__device__ float g_negT[(size_t)NN * NN];   // -cost^T
__device__ float g_tau_col[NN];
__device__ float g_beta[(size_t)NN * DD];
__device__ float g_alpha[(size_t)NN * DD];
__device__ float g_v1[DD];
__device__ float g_v2[DD];
__device__ float g_y;

// ---------------- warp helpers ----------------
__device__ __forceinline__ float warpRedSum(float v) {
#pragma unroll
    for (int o = 16; o > 0; o >>= 1) v += __shfl_xor_sync(0xffffffffu, v, o);
    return v;
}
__device__ __forceinline__ float warpRedMax(float v) {
#pragma unroll
    for (int o = 16; o > 0; o >>= 1) v = fmaxf(v, __shfl_xor_sync(0xffffffffu, v, o));
    return v;
}

// exclusive scan of per-thread counts over 256 threads
__device__ __forceinline__ int blockScanExcl(int cnt, int& total, int tid) {
    __shared__ int warp_tot[8];
    const unsigned mask = 0xffffffffu;
    int lane = tid & 31, w = tid >> 5;
    int incl = cnt;
#pragma unroll
    for (int o = 1; o < 32; o <<= 1) {
        int n = __shfl_up_sync(mask, incl, o);
        if (lane >= o) incl += n;
    }
    if (lane == 31) warp_tot[w] = incl;
    __syncthreads();
    if (w == 0) {
        int t = (lane < 8) ? warp_tot[lane] : 0;
#pragma unroll
        for (int o = 1; o < 8; o <<= 1) {
            int n = __shfl_up_sync(mask, t, o);
            if (lane >= o) t += n;
        }
        if (lane < 8) warp_tot[lane] = t;
    }
    __syncthreads();
    int warp_off = (w == 0) ? 0 : warp_tot[w - 1];
    total = warp_tot[7];
    __syncthreads();
    return warp_off + incl - cnt;
}

// ---------------- register-resident sparsemax core ----------------
// Row lives in 16 registers per thread. Start Michelot at tau0 = max-1 (valid
// lower bound: p_max <= 1). ~3-4 iterations, one barrier each.
template <bool NEG, bool WRITE_ALIGN>
__device__ __forceinline__ void spmax_core(const float* __restrict__ xrow,
                                           float* __restrict__ align_row,
                                           float* __restrict__ tau_store,
                                           const float* __restrict__ V,
                                           float* __restrict__ mix_out, int row) {
    __shared__ float red[8 + 64];     // [0..7] max partials; [8..] (sum,count) x 2 parities
    __shared__ float s_p[CAPS];
    __shared__ unsigned short s_j[CAPS];
    int tid = threadIdx.x;   // 256

    // coalesced load into registers; running max
    float x[16];
    float vmax = -3.0e38f;
#pragma unroll
    for (int k = 0; k < 4; k++) {
        float4 v = *(const float4*)(xrow + tid * 4 + k * 1024);
        if (NEG) { v.x = -v.x; v.y = -v.y; v.z = -v.z; v.w = -v.w; }
        x[k * 4 + 0] = v.x; x[k * 4 + 1] = v.y;
        x[k * 4 + 2] = v.z; x[k * 4 + 3] = v.w;
        vmax = fmaxf(vmax, fmaxf(fmaxf(v.x, v.y), fmaxf(v.z, v.w)));
    }

    // block max (1 barrier)
    float m = warpRedMax(vmax);
    if ((tid & 31) == 0) red[tid >> 5] = m;
    __syncthreads();
    float bm = red[0];
#pragma unroll
    for (int i = 1; i < 8; i++) bm = fmaxf(bm, red[i]);

    float tau = bm - 1.0f;     // tau0 <= tau*  -> support superset, Michelot valid
    int kprev = -1;

    for (int it = 0; it < 64; ++it) {
        float ls = 0.f, lc = 0.f;
#pragma unroll
        for (int s = 0; s < 16; s++) {
            float v = x[s];
            if (v > tau) { ls += v; lc += 1.0f; }
        }
        ls = warpRedSum(ls);
        lc = warpRedSum(lc);
        int p = it & 1;
        float* buf = red + 8 + p * 32;
        if ((tid & 31) == 0) { buf[tid >> 5] = ls; buf[8 + (tid >> 5)] = lc; }
        __syncthreads();
        float S = 0.f, K = 0.f;
#pragma unroll
        for (int i = 0; i < 8; i++) { S += buf[i]; K += buf[8 + i]; }
        int k = (int)K;
        if (k == kprev) break;           // uniform across block (same S,K everywhere)
        tau = (S - 1.0f) / K;
        kprev = k;
    }

    if (tau_store && tid == 0) *tau_store = tau;

    // alignment row straight from registers (coalesced, no re-read)
    if (WRITE_ALIGN) {
#pragma unroll
        for (int k = 0; k < 4; k++) {
            float4 o;
            o.x = fmaxf(x[k * 4 + 0] - tau, 0.f);
            o.y = fmaxf(x[k * 4 + 1] - tau, 0.f);
            o.z = fmaxf(x[k * 4 + 2] - tau, 0.f);
            o.w = fmaxf(x[k * 4 + 3] - tau, 0.f);
            *(float4*)(align_row + tid * 4 + k * 1024) = o;
        }
    }

    // deterministic support compaction
    int cnt = 0;
#pragma unroll
    for (int s = 0; s < 16; s++)
        if (x[s] > tau) cnt++;
    int nnz;
    int base = blockScanExcl(cnt, nnz, tid);
    if (nnz <= CAPS) {
        int pos = base;
#pragma unroll
        for (int s = 0; s < 16; s++) {
            if (x[s] > tau) {
                s_p[pos] = x[s] - tau;
                s_j[pos] = (unsigned short)(tid * 4 + (s >> 2) * 1024 + (s & 3));
                pos++;
            }
        }
    }
    __syncthreads();

    // mix: out[row, d] = sum_{n} p_n * V[j_n, d], d = tid (coalesced V reads, L2-hot)
    float acc = 0.f;
    if (nnz <= CAPS) {
#pragma unroll 4
        for (int n = 0; n < nnz; n++)
            acc = fmaf(s_p[n], V[(size_t)s_j[n] * DD + tid], acc);
    } else {
        for (int j = 0; j < NN; j++) {
            float xv = NEG ? -xrow[j] : xrow[j];
            float p = xv - tau;
            if (p > 0.f) acc = fmaf(p, V[(size_t)j * DD + tid], acc);
        }
    }
    mix_out[(size_t)row * DD + tid] = acc;
}

// ---------------- kernels ----------------
__global__ void zero_kernel() {
    int t = threadIdx.x;
    g_v1[t] = 0.f;
    g_v2[t] = 0.f;
}

__global__ void transpose_neg_kernel(const float* __restrict__ in) {
    __shared__ float t[32][33];
    int bx = blockIdx.x * 32, by = blockIdx.y * 32;
    int tx = threadIdx.x, ty = threadIdx.y;
#pragma unroll
    for (int dy = 0; dy < 32; dy += 8)
        t[ty + dy][tx] = -in[(size_t)(by + ty + dy) * NN + bx + tx];
    __syncthreads();
#pragma unroll
    for (int dy = 0; dy < 32; dy += 8)
        g_negT[(size_t)(bx + ty + dy) * NN + by + tx] = t[tx][ty + dy];
}

__global__ __launch_bounds__(256) void spmax_row_kernel(const float* __restrict__ cost,
                                                        float* __restrict__ a0,
                                                        const float* __restrict__ colvecs) {
    int row = blockIdx.x;
    spmax_core<true, true>(cost + (size_t)row * NN, a0 + (size_t)row * NN, nullptr,
                           colvecs, g_beta, row);
}

__global__ __launch_bounds__(256) void spmax_col_kernel(const float* __restrict__ rowvecs) {
    int row = blockIdx.x;   // column index of the original cost matrix
    spmax_core<false, false>(g_negT + (size_t)row * NN, nullptr, &g_tau_col[row],
                             rowvecs, g_alpha, row);
}

// align1[i, j] = max(-cost[i,j] - tau_col[j], 0)
__global__ void col_align_kernel(const float* __restrict__ cost, float* __restrict__ out) {
    size_t idx = ((size_t)blockIdx.x * blockDim.x + threadIdx.x) * 4;
    int j = (int)(idx & (NN - 1));
    float4 c = *(const float4*)(cost + idx);
    float4 o;
    o.x = fmaxf(-c.x - g_tau_col[j + 0], 0.f);
    o.y = fmaxf(-c.y - g_tau_col[j + 1], 0.f);
    o.z = fmaxf(-c.z - g_tau_col[j + 2], 0.f);
    o.w = fmaxf(-c.w - g_tau_col[j + 3], 0.f);
    *(float4*)(out + idx) = o;
}

// partial sums of leaky_relu(X @ W + b) over 16 rows per block
__global__ __launch_bounds__(256) void g_mean_kernel(const float* __restrict__ Wg,
                                                     const float* __restrict__ bg,
                                                     int which) {
    const float* Xall = which ? g_alpha : g_beta;
    float* gv = which ? g_v2 : g_v1;
    __shared__ float xs[16 * 256];
    int tid = threadIdx.x;
    size_t r0 = (size_t)blockIdx.x * 16;
#pragma unroll
    for (int r = 0; r < 16; r++) xs[r * 256 + tid] = Xall[(r0 + r) * 256 + tid];
    __syncthreads();

    float acc[16];
#pragma unroll
    for (int r = 0; r < 16; r++) acc[r] = 0.f;
#pragma unroll 4
    for (int k = 0; k < 256; k++) {
        float w = Wg[k * 256 + tid];
#pragma unroll
        for (int r = 0; r < 16; r++) acc[r] = fmaf(xs[r * 256 + k], w, acc[r]);
    }
    float bb = bg[tid], s = 0.f;
#pragma unroll
    for (int r = 0; r < 16; r++) {
        float z = acc[r] + bb;
        s += (z > 0.f) ? z : 0.2f * z;
    }
    atomicAdd(&gv[tid], s);
}

__global__ void cosine_kernel() {
    __shared__ float red[40];
    int tid = threadIdx.x;
    float v1 = g_v1[tid] * (1.0f / NN);
    float v2 = g_v2[tid] * (1.0f / NN);
    float d = v1 * v2, a = v1 * v1, b = v2 * v2;
    d = warpRedSum(d); a = warpRedSum(a); b = warpRedSum(b);
    if ((tid & 31) == 0) {
        red[tid >> 5] = d; red[8 + (tid >> 5)] = a; red[16 + (tid >> 5)] = b;
    }
    __syncthreads();
    if (tid == 0) {
        float D = 0.f, A = 0.f, B = 0.f;
#pragma unroll
        for (int i = 0; i < 8; i++) { D += red[i]; A += red[8 + i]; B += red[16 + i]; }
        g_y = 1.0f - D / (sqrtf(A) * sqrtf(B) + 1e-8f);
    }
}

__global__ void fill_kernel(float* __restrict__ out) {
    float y = g_y;
    size_t idx = ((size_t)blockIdx.x * blockDim.x + threadIdx.x) * 4;
    *(float4*)(out + idx) = make_float4(y, y, y, y);
}

// ---------------- launch ----------------
extern "C" void kernel_launch(void* const* d_in, const int* in_sizes, int n_in,
                              void* d_out, int out_size) {
    const float* row_vecs    = (const float*)d_in[0];
    const float* column_vecs = (const float*)d_in[1];
    const float* cost        = (const float*)d_in[2];
    const float* W_G         = (const float*)d_in[3];
    const float* b_G         = (const float*)d_in[4];

    float* out      = (float*)d_out;
    float* cost_out = out;
    float* a0       = out + (size_t)NN * NN;
    float* a1       = out + 2 * (size_t)NN * NN;

    (void)in_sizes; (void)n_in; (void)out_size;

    zero_kernel<<<1, 256>>>();
    transpose_neg_kernel<<<dim3(NN / 32, NN / 32), dim3(32, 8)>>>(cost);
    spmax_row_kernel<<<NN, 256>>>(cost, a0, column_vecs);
    spmax_col_kernel<<<NN, 256>>>(row_vecs);
    col_align_kernel<<<(NN * (size_t)NN) / (4 * 256), 256>>>(cost, a1);
    g_mean_kernel<<<NN / 16, 256>>>(W_G, b_G, 0);
    g_mean_kernel<<<NN / 16, 256>>>(W_G, b_G, 1);
    cosine_kernel<<<1, 256>>>();
    fill_kernel<<<(NN * (size_t)NN) / (4 * 256), 256>>>(cost_out);
}